// round 4
// baseline (speedup 1.0000x reference)
#include <cuda_runtime.h>
#include <cuda_bf16.h>
#include <cstdint>

#define DEPTH_DIM 256
#define CAPW      64             // points per 4-pixel warp-bin (lambda ~ 4.4)
#define MAX_WBINS (1 << 18)      // up to 1M pixels / 4

__device__ int   g_cnt[MAX_WBINS];                 // zero-init at load; self-reset
__device__ uint2 g_binData[MAX_WBINS * CAPW];      // {pix2<<16|depth, conf bits}

__device__ __forceinline__ float ex2_fast(float x) {
    float y;
    asm("ex2.approx.ftz.f32 %0, %1;" : "=f"(y) : "f"(x));
    return y;
}

// ---------------------------------------------------------------------------
// K1: scatter points into 4-pixel warp-bins (order-free slot via atomicAdd)
// ---------------------------------------------------------------------------
__global__ void bin_kernel(const int2* __restrict__ pos,
                           const int*  __restrict__ depth,
                           const float* __restrict__ conf,
                           const int*  __restrict__ pW, int npts) {
    int i = blockIdx.x * blockDim.x + threadIdx.x;
    if (i >= npts) return;
    int W = __ldg(pW);
    int2 uv = __ldg(&pos[i]);
    int lin = uv.y * W + uv.x;
    int wbin = lin >> 2;
    int slot = atomicAdd(&g_cnt[wbin], 1);
    if (slot < CAPW) {
        uint2 v;
        v.x = ((unsigned)(lin & 3) << 16) | (unsigned)__ldg(&depth[i]);
        v.y = __float_as_uint(__ldg(&conf[i]));
        g_binData[wbin * CAPW + slot] = v;
    }
}

// ---------------------------------------------------------------------------
// K2: fused accumulate + transposed write.
//   Block = 32 pixels. Warp w owns warp-bin (block*8+w) = pixels 4w..4w+3.
//   Each warp touches ONLY its own bin's points (no skip-scan).
//   Lane L owns depths d = L + 32m; smem tile stride 33 -> conflict-free
//   for both the column store and the row read.
//   Counters are reset after reading: state is 0 at entry and exit of every
//   graph replay (deterministic).
// ---------------------------------------------------------------------------
__global__ void fused_kernel(float* __restrict__ out, int HW) {
    __shared__ float tile[DEPTH_DIM][33];
    __shared__ uint2 spts[8][CAPW];

    int tid  = threadIdx.x;
    int lane = tid & 31;
    int w    = tid >> 5;
    int wbin = blockIdx.x * 8 + w;
    bool valid = (wbin * 4) < HW;

    int cnt = 0;
    if (valid) {
        cnt = min(g_cnt[wbin], CAPW);
        if (lane == 0) g_cnt[wbin] = 0;          // reset for next launch
    }
    for (int t = lane; t < cnt; t += 32)
        spts[w][t] = g_binData[wbin * CAPW + t];
    __syncwarp();

    // -0.5 * h^2 * log2(e),  h = 6/255
    const float C = -0.5f * (6.0f / 255.0f) * (6.0f / 255.0f) * 1.4426950408889634f;

    float acc[4][8];
#pragma unroll
    for (int a = 0; a < 4; ++a)
#pragma unroll
        for (int m = 0; m < 8; ++m) acc[a][m] = 0.0f;

    for (int t = 0; t < cnt; ++t) {
        uint2 v = spts[w][t];                    // 8B broadcast read
        int   jj    = (int)(v.x >> 16);
        int   pd    = (int)(v.x & 0xffff);
        float sigma = __uint_as_float(v.y);
        float na2   = __fdividef(C, sigma * sigma);

        float g[8];
        float s = 0.0f;
#pragma unroll
        for (int m = 0; m < 8; ++m) {
            int d = lane + 32 * m;
            int k = d - pd - (d > pd);           // dup k=0 at d=pd,pd+1 (matches ref)
            float kf = (float)k;
            g[m] = ex2_fast(na2 * kf * kf);
            s = fmaf(g[m], g[m], s);
        }
#pragma unroll
        for (int o = 16; o > 0; o >>= 1)
            s += __shfl_xor_sync(0xffffffffu, s, o);
        float inv = rsqrtf(s);                   // s >= 1 (k=0 term), no eps clamp

        if (jj == 0) {
#pragma unroll
            for (int m = 0; m < 8; ++m) acc[0][m] = fmaf(g[m], inv, acc[0][m]);
        } else if (jj == 1) {
#pragma unroll
            for (int m = 0; m < 8; ++m) acc[1][m] = fmaf(g[m], inv, acc[1][m]);
        } else if (jj == 2) {
#pragma unroll
            for (int m = 0; m < 8; ++m) acc[2][m] = fmaf(g[m], inv, acc[2][m]);
        } else {
#pragma unroll
            for (int m = 0; m < 8; ++m) acc[3][m] = fmaf(g[m], inv, acc[3][m]);
        }
    }

    // stage to smem: column j = w*4+jj, bank = (lane + j) % 32 -> conflict-free
#pragma unroll
    for (int jj = 0; jj < 4; ++jj)
#pragma unroll
        for (int m = 0; m < 8; ++m)
            tile[lane + 32 * m][w * 4 + jj] = acc[jj][m];
    __syncthreads();

    // coalesced output: each warp writes 32 consecutive pixels per depth row
    int p = blockIdx.x * 32 + lane;
    if (p < HW) {
#pragma unroll
        for (int m = 0; m < 32; ++m) {
            int d = w + m * 8;
            out[(size_t)d * HW + p] = tile[d][lane];
        }
    }
}

// ---------------------------------------------------------------------------
// Launch
// ---------------------------------------------------------------------------
extern "C" void kernel_launch(void* const* d_in, const int* in_sizes, int n_in,
                              void* d_out, int out_size) {
    const int2*  pos   = (const int2*)d_in[0];   // [N,2] int32 (u=x, v=y)
    const int*   depth = (const int*)d_in[1];    // [N,1] int32
    const float* conf  = (const float*)d_in[2];  // [N,1] float32
    const int*   pW    = (const int*)d_in[4];    // feat_w scalar

    int npts   = in_sizes[1];
    int HW     = out_size / DEPTH_DIM;
    int nblk   = (HW + 31) / 32;                 // 32 pixels (8 warp-bins) per block

    bin_kernel<<<(npts + 255) / 256, 256>>>(pos, depth, conf, pW, npts);
    fused_kernel<<<nblk, 256>>>((float*)d_out, HW);
}